// round 14
// baseline (speedup 1.0000x reference)
#include <cuda_runtime.h>
#include <cstdint>

#define N_ATOMS 4096
#define L_WORDS 65536
#define DD 10
#define KS 23
#define KSPLIT 2
#define KCHUNK (N_ATOMS / KSPLIT)   // 2048
#define NT 256
#define SMEM_BYTES 81920            // 40 * (KCHUNK/8) * 8
#define MV0ROWS 4                   // k_mv0 rows/warp
#define MV0TILE 32
#define MVROWS 8                    // k_mv rows/warp (R7-proven tile)
#define MVTILE 64
#define CROWS 128                   // CNN rows/block (2 threads/row)

typedef unsigned long long ull;

// ---------------- scratch ----------------
__device__ float g_xs[N_ATOMS * DD];
__device__ ull   g_hs[8 * 5 * (N_ATOMS / 8)];        // hs f32x2, [k8][p][m/8]
__device__ uint4 g_Ab[(size_t)N_ATOMS * N_ATOMS / 8];// A bf16
__device__ float g_pp[KSPLIT][N_ATOMS * DD];
__device__ float g_cnn[2][L_WORDS * DD];
__device__ float g_comp[DD];
__device__ float g_hatt[DD];
__device__ float g_part[256 * DD];

// ---------------- helpers ----------------
__device__ __forceinline__ ull pack2(float x, float y) {
    ull r; asm("mov.b64 %0, {%1, %2};" : "=l"(r) : "f"(x), "f"(y)); return r;
}
__device__ __forceinline__ void unpack2(ull v, float& x, float& y) {
    asm("mov.b64 {%0, %1}, %2;" : "=f"(x), "=f"(y) : "l"(v));
}
__device__ __forceinline__ void fma2(ull& d, ull a, ull b) {
    asm("fma.rn.f32x2 %0, %1, %2, %0;" : "+l"(d) : "l"(a), "l"(b));
}
__device__ __forceinline__ ull add2(ull a, ull b) {
    ull r; asm("add.rn.f32x2 %0, %1, %2;" : "=l"(r) : "l"(a), "l"(b)); return r;
}
__device__ __forceinline__ unsigned bfpack(float lo, float hi) {
    unsigned r;
    asm("cvt.rn.bf16x2.f32 %0, %1, %2;" : "=r"(r) : "f"(hi), "f"(lo));
    return r;
}

__device__ __forceinline__ void hs_store(int m, const float* x,
                                         const float* Wgl, const float* bgl) {
    int k8 = m & 7, base = m >> 3;
#pragma unroll
    for (int p = 0; p < 5; p++) {
        float h0 = bgl[2 * p], h1 = bgl[2 * p + 1];
#pragma unroll
        for (int c = 0; c < DD; c++) {
            h0 = fmaf(x[c], Wgl[(2 * p) * DD + c], h0);
            h1 = fmaf(x[c], Wgl[(2 * p + 1) * DD + c], h1);
        }
        g_hs[(k8 * 5 + p) * (N_ATOMS / 8) + base] =
            pack2(fmaxf(h0, 0.f), fmaxf(h1, 0.f));
    }
}

__device__ __forceinline__ void fill_hs(ull* sh, int kb) {
    for (int i = threadIdx.x; i < 40 * (KCHUNK / 8); i += NT) {
        int kp = i / (KCHUNK / 8), j = i % (KCHUNK / 8);
        sh[i] = g_hs[kp * (N_ATOMS / 8) + kb * (KCHUNK / 8) + j];
    }
    __syncthreads();
}

// ---------------- GNN chain kernels ----------------
__global__ void __launch_bounds__(NT) k_pre(const int* __restrict__ fp,
                                            const float* __restrict__ embf,
                                            const float* __restrict__ Wg,
                                            const float* __restrict__ bg) {
    int m = blockIdx.x * NT + threadIdx.x;
    float x[DD];
#pragma unroll
    for (int c = 0; c < DD; c++) {
        x[c] = embf[(size_t)fp[m] * DD + c];
        g_xs[m * DD + c] = x[c];
    }
    hs_store(m, x, Wg, bg);
}

__global__ void __launch_bounds__(NT) k_hs(const float* __restrict__ Wgl,
                                           const float* __restrict__ bgl) {
    int m = blockIdx.x * NT + threadIdx.x;
    float x[DD];
#pragma unroll
    for (int c = 0; c < DD; c++) {
        float v = g_xs[m * DD + c] + g_pp[0][m * DD + c] + g_pp[1][m * DD + c];
        g_xs[m * DD + c] = v;
        x[c] = v;
    }
    hs_store(m, x, Wgl, bgl);
}

// layer0 mv: fp32 A read, bf16 write, 32-row tiles, grid 256 (R11 config)
__global__ void __launch_bounds__(NT, 2) k_mv0(const float* __restrict__ A) {
    extern __shared__ char smem_raw[];
    ull* sh = (ull*)smem_raw;
    const int tid = threadIdx.x;
    const int rowblk = blockIdx.x & 127, kb = blockIdx.x >> 7;
    fill_hs(sh, kb);

    const int warp = tid >> 5, lane = tid & 31;
    const int row0 = rowblk * MV0TILE + warp * MV0ROWS;
    float* pout = g_pp[kb];

    const float4* Af[MV0ROWS];
    uint4* Ao[MV0ROWS];
#pragma unroll
    for (int r = 0; r < MV0ROWS; r++) {
        Af[r] = (const float4*)A + (size_t)(row0 + r) * (N_ATOMS / 4) + kb * (KCHUNK / 4);
        Ao[r] = g_Ab + (size_t)(row0 + r) * (N_ATOMS / 8) + kb * (KCHUNK / 8);
    }

    ull acc[MV0ROWS][5];
#pragma unroll
    for (int r = 0; r < MV0ROWS; r++)
#pragma unroll
        for (int p = 0; p < 5; p++) acc[r][p] = 0ull;

    for (int it = 0; it < KCHUNK / 256; it++) {
        int q = it * 32 + lane;
        float4 lo[MV0ROWS], hi[MV0ROWS];
#pragma unroll
        for (int r = 0; r < MV0ROWS; r++) {
            lo[r] = Af[r][2 * q];
            hi[r] = Af[r][2 * q + 1];
            uint4 o;
            o.x = bfpack(lo[r].x, lo[r].y);
            o.y = bfpack(lo[r].z, lo[r].w);
            o.z = bfpack(hi[r].x, hi[r].y);
            o.w = bfpack(hi[r].z, hi[r].w);
            Ao[r][q] = o;
        }
#pragma unroll
        for (int k8 = 0; k8 < 8; k8++) {
            ull h[5];
#pragma unroll
            for (int p = 0; p < 5; p++)
                h[p] = sh[(k8 * 5 + p) * (KCHUNK / 8) + q];
#pragma unroll
            for (int r = 0; r < MV0ROWS; r++) {
                float av = (k8 == 0) ? lo[r].x : (k8 == 1) ? lo[r].y
                         : (k8 == 2) ? lo[r].z : (k8 == 3) ? lo[r].w
                         : (k8 == 4) ? hi[r].x : (k8 == 5) ? hi[r].y
                         : (k8 == 6) ? hi[r].z : hi[r].w;
                ull v = pack2(av, av);
#pragma unroll
                for (int p = 0; p < 5; p++) fma2(acc[r][p], v, h[p]);
            }
        }
    }

#pragma unroll
    for (int r = 0; r < MV0ROWS; r++) {
        float f[DD];
#pragma unroll
        for (int p = 0; p < 5; p++) unpack2(acc[r][p], f[2 * p], f[2 * p + 1]);
#pragma unroll
        for (int d = 0; d < DD; d++)
#pragma unroll
            for (int o = 16; o > 0; o >>= 1)
                f[d] += __shfl_down_sync(0xffffffffu, f[d], o);
        if (lane == 0)
#pragma unroll
            for (int d = 0; d < DD; d++) pout[(row0 + r) * DD + d] = f[d];
    }
}

// layers 1,2 mv: bf16 A, 64-row tiles (8 rows/warp), uint2 half-loads, grid 128
__global__ void __launch_bounds__(NT, 2) k_mv() {
    extern __shared__ char smem_raw[];
    ull* sh = (ull*)smem_raw;
    const int tid = threadIdx.x;
    const int rowblk = blockIdx.x & 63, kb = blockIdx.x >> 6;
    fill_hs(sh, kb);

    const int warp = tid >> 5, lane = tid & 31;
    const int row0 = rowblk * MVTILE + warp * MVROWS;
    float* pout = g_pp[kb];
    const int rstride2 = N_ATOMS / 4;   // uint2 stride per row
    const uint2* Abase = (const uint2*)g_Ab + (size_t)row0 * rstride2 + kb * (KCHUNK / 4);

    ull acc[MVROWS][5];
#pragma unroll
    for (int r = 0; r < MVROWS; r++)
#pragma unroll
        for (int p = 0; p < 5; p++) acc[r][p] = 0ull;

    for (int it = 0; it < KCHUNK / 256; it++) {
        int q = it * 32 + lane;           // 8-col group index
        // first half: k8 0..3 (uint2 = 4 bf16x2 cols)
        uint2 a0[MVROWS];
#pragma unroll
        for (int r = 0; r < MVROWS; r++) a0[r] = Abase[r * rstride2 + 2 * q];
#pragma unroll
        for (int k8 = 0; k8 < 4; k8++) {
            ull h[5];
#pragma unroll
            for (int p = 0; p < 5; p++)
                h[p] = sh[(k8 * 5 + p) * (KCHUNK / 8) + q];
#pragma unroll
            for (int r = 0; r < MVROWS; r++) {
                unsigned w = (k8 < 2) ? a0[r].x : a0[r].y;
                float av = (k8 & 1) ? __uint_as_float(w & 0xffff0000u)
                                    : __uint_as_float(w << 16);
                ull v = pack2(av, av);
#pragma unroll
                for (int p = 0; p < 5; p++) fma2(acc[r][p], v, h[p]);
            }
        }
        // second half: k8 4..7
        uint2 a1[MVROWS];
#pragma unroll
        for (int r = 0; r < MVROWS; r++) a1[r] = Abase[r * rstride2 + 2 * q + 1];
#pragma unroll
        for (int k8 = 4; k8 < 8; k8++) {
            ull h[5];
#pragma unroll
            for (int p = 0; p < 5; p++)
                h[p] = sh[(k8 * 5 + p) * (KCHUNK / 8) + q];
#pragma unroll
            for (int r = 0; r < MVROWS; r++) {
                unsigned w = (k8 < 6) ? a1[r].x : a1[r].y;
                float av = (k8 & 1) ? __uint_as_float(w & 0xffff0000u)
                                    : __uint_as_float(w << 16);
                ull v = pack2(av, av);
#pragma unroll
                for (int p = 0; p < 5; p++) fma2(acc[r][p], v, h[p]);
            }
        }
    }

#pragma unroll
    for (int r = 0; r < MVROWS; r++) {
        float f[DD];
#pragma unroll
        for (int p = 0; p < 5; p++) unpack2(acc[r][p], f[2 * p], f[2 * p + 1]);
#pragma unroll
        for (int d = 0; d < DD; d++)
#pragma unroll
            for (int o = 16; o > 0; o >>= 1)
                f[d] += __shfl_down_sync(0xffffffffu, f[d], o);
        if (lane == 0)
#pragma unroll
            for (int d = 0; d < DD; d++) pout[(row0 + r) * DD + d] = f[d];
    }
}

__global__ void __launch_bounds__(512) k_comp(const float* __restrict__ Wat,
                                              const float* __restrict__ bat) {
    __shared__ float red[512 * DD];
    int tid = threadIdx.x;
    float acc[DD];
#pragma unroll
    for (int d = 0; d < DD; d++) acc[d] = 0.f;
    for (int n = tid; n < N_ATOMS; n += 512)
#pragma unroll
        for (int d = 0; d < DD; d++)
            acc[d] += g_xs[n * DD + d] + g_pp[0][n * DD + d] + g_pp[1][n * DD + d];
#pragma unroll
    for (int d = 0; d < DD; d++) red[tid * DD + d] = acc[d];
    __syncthreads();
    for (int s = 256; s > 0; s >>= 1) {
        if (tid < s) {
#pragma unroll
            for (int d = 0; d < DD; d++) red[tid * DD + d] += red[(tid + s) * DD + d];
        }
        __syncthreads();
    }
    if (tid < DD) {
        float comp = red[tid] * (1.f / N_ATOMS);
        g_comp[tid] = comp;
        float hv = bat[tid];
#pragma unroll
        for (int c = 0; c < DD; c++)
            hv = fmaf(red[c] * (1.f / N_ATOMS), Wat[tid * DD + c], hv);
        g_hatt[tid] = fmaxf(hv, 0.f);
    }
}

// ---------------- CNN chain ----------------
// layer 0 gathers embw[words[.]] directly into sIn (gather kernel eliminated)
__global__ void __launch_bounds__(NT) k_cnn(int layer, const float* __restrict__ Wc,
                                            const float* __restrict__ bc,
                                            const int* __restrict__ words,
                                            const float* __restrict__ embw) {
    __shared__ float sIn[(CROWS + 22) * 11];
    __shared__ ull sW[KS * 50];
    __shared__ ull red[CROWS * 5];
    const int tid = threadIdx.x;
    const int row = tid & (CROWS - 1);
    const int half = tid >> 7;
    const float* in = g_cnn[layer & 1];
    float*       o  = g_cnn[(layer & 1) ^ 1];
    const float* W  = Wc + layer * KS * KS;
    const float bias = bc[layer];

    for (int i = tid; i < KS * 50; i += NT) {
        int dl = i / 50, rem = i % 50, c = rem / 5, p = rem % 5;
        sW[i] = pack2(W[dl * KS + 11 + c - 2 * p], W[dl * KS + 11 + c - 2 * p - 1]);
    }
    int base = blockIdx.x * CROWS - 11;
    if (layer == 0) {
        for (int i = tid; i < (CROWS + 22) * DD; i += NT) {
            int rr = i / DD, c = i - rr * DD;
            int g = base + rr;
            sIn[rr * 11 + c] =
                (g >= 0 && g < L_WORDS) ? embw[(size_t)words[g] * DD + c] : 0.f;
        }
    } else {
        for (int i = tid; i < (CROWS + 22) * DD; i += NT) {
            int rr = i / DD, c = i - rr * DD;
            int g = base + rr;
            sIn[rr * 11 + c] = (g >= 0 && g < L_WORDS) ? in[g * DD + c] : 0.f;
        }
    }
    __syncthreads();

    ull acc[5];
    ull b2 = pack2(bias, bias);
#pragma unroll
    for (int p = 0; p < 5; p++) acc[p] = (half == 0) ? b2 : 0ull;
    const int c0 = half * 5;
#pragma unroll 1
    for (int dl = 0; dl < KS; dl++) {
#pragma unroll
        for (int cc = 0; cc < 5; cc++) {
            int c = c0 + cc;
            float xv = sIn[(row + dl) * 11 + c];
            ull x2 = pack2(xv, xv);
#pragma unroll
            for (int p = 0; p < 5; p++) fma2(acc[p], x2, sW[dl * 50 + c * 5 + p]);
        }
    }

    if (half == 1) {
#pragma unroll
        for (int p = 0; p < 5; p++) red[row * 5 + p] = acc[p];
    }
    __syncthreads();
    if (half == 0) {
        int grow = blockIdx.x * CROWS + row;
#pragma unroll
        for (int p = 0; p < 5; p++) {
            ull s = add2(acc[p], red[row * 5 + p]);
            float v0, v1;
            unpack2(s, v0, v1);
            o[grow * DD + 2 * p]     = fmaxf(v0, 0.f);
            o[grow * DD + 2 * p + 1] = fmaxf(v1, 0.f);
        }
    }
}

// ---------------- join kernels ----------------
__global__ void __launch_bounds__(NT) k_att(const float* __restrict__ Wat,
                                            const float* __restrict__ bat) {
    __shared__ float sWat[DD * DD], sbv[DD], shv[DD];
    __shared__ float red[NT * DD];
    const int tid = threadIdx.x;
    if (tid < DD * DD) sWat[tid] = Wat[tid];
    if (tid < DD) { sbv[tid] = bat[tid]; shv[tid] = g_hatt[tid]; }
    __syncthreads();

    int l = blockIdx.x * NT + tid;
    const float* in = g_cnn[1];
    float x[DD];
#pragma unroll
    for (int c = 0; c < DD; c++) x[c] = in[l * DD + c];
    float hp[DD], wl = 0.f;
#pragma unroll
    for (int u = 0; u < DD; u++) {
        float v = sbv[u];
#pragma unroll
        for (int c = 0; c < DD; c++) v = fmaf(x[c], sWat[u * DD + c], v);
        v = fmaxf(v, 0.f);
        hp[u] = v;
        wl = fmaf(shv[u], v, wl);
    }
    wl = tanhf(wl);
#pragma unroll
    for (int d = 0; d < DD; d++) red[tid * DD + d] = wl * hp[d];
    __syncthreads();
    for (int s = 128; s > 0; s >>= 1) {
        if (tid < s) {
#pragma unroll
            for (int d = 0; d < DD; d++) red[tid * DD + d] += red[(tid + s) * DD + d];
        }
        __syncthreads();
    }
    if (tid < DD) g_part[blockIdx.x * DD + tid] = red[tid];
}

__global__ void __launch_bounds__(NT) k_final(const float* __restrict__ Wout,
                                              const float* __restrict__ bout,
                                              const float* __restrict__ Wint,
                                              const float* __restrict__ bint,
                                              float* __restrict__ out) {
    __shared__ float red[NT * DD];
    __shared__ float cat[20];
    const int tid = threadIdx.x;
#pragma unroll
    for (int d = 0; d < DD; d++) red[tid * DD + d] = g_part[tid * DD + d];
    __syncthreads();
    for (int s = 128; s > 0; s >>= 1) {
        if (tid < s) {
#pragma unroll
            for (int d = 0; d < DD; d++) red[tid * DD + d] += red[(tid + s) * DD + d];
        }
        __syncthreads();
    }
    if (tid < DD) cat[tid] = g_comp[tid];
    if (tid >= DD && tid < 20) cat[tid] = red[tid - DD] * (1.f / L_WORDS);
    __syncthreads();
    if (tid < 32) {
        for (int j = 0; j < 3; j++) {
            float v = 0.f;
            if (tid < 20) {
                v = bout[j * 20 + tid];
                for (int c = 0; c < 20; c++)
                    v = fmaf(cat[c], Wout[j * 400 + tid * 20 + c], v);
                v = fmaxf(v, 0.f);
            }
            __syncwarp();
            if (tid < 20) cat[tid] = v;
            __syncwarp();
        }
        if (tid < 2) {
            float v = bint[tid];
            for (int c = 0; c < 20; c++) v = fmaf(cat[c], Wint[tid * 20 + c], v);
            out[tid] = v;
        }
    }
}

// ---------------- launch: two-branch graph ----------------
extern "C" void kernel_launch(void* const* d_in, const int* in_sizes, int n_in,
                              void* d_out, int out_size) {
    const int*   fp    = (const int*)d_in[0];
    const float* A     = (const float*)d_in[1];
    const int*   words = (const int*)d_in[2];
    const float* embf  = (const float*)d_in[3];
    const float* embw  = (const float*)d_in[4];
    const float* Wg    = (const float*)d_in[5];
    const float* bg    = (const float*)d_in[6];
    const float* Wc    = (const float*)d_in[7];
    const float* bc    = (const float*)d_in[8];
    const float* Wat   = (const float*)d_in[9];
    const float* bat   = (const float*)d_in[10];
    const float* Wout  = (const float*)d_in[11];
    const float* bout  = (const float*)d_in[12];
    const float* Wint  = (const float*)d_in[13];
    const float* bint  = (const float*)d_in[14];
    float* out = (float*)d_out;

    cudaFuncSetAttribute(k_mv0, cudaFuncAttributeMaxDynamicSharedMemorySize, SMEM_BYTES);
    cudaFuncSetAttribute(k_mv,  cudaFuncAttributeMaxDynamicSharedMemorySize, SMEM_BYTES);

    cudaStream_t sC;
    cudaStreamCreateWithFlags(&sC, cudaStreamNonBlocking);
    cudaEvent_t eFork, eJoin;
    cudaEventCreateWithFlags(&eFork, cudaEventDisableTiming);
    cudaEventCreateWithFlags(&eJoin, cudaEventDisableTiming);

    cudaEventRecord(eFork, 0);
    cudaStreamWaitEvent(sC, eFork, 0);

    // ----- CNN branch (gather fused into layer 0) -----
    k_cnn<<<L_WORDS / CROWS, NT, 0, sC>>>(0, Wc, bc, words, embw);
    k_cnn<<<L_WORDS / CROWS, NT, 0, sC>>>(1, Wc, bc, words, embw);
    k_cnn<<<L_WORDS / CROWS, NT, 0, sC>>>(2, Wc, bc, words, embw);
    cudaEventRecord(eJoin, sC);

    // ----- GNN branch -----
    k_pre<<<N_ATOMS / NT, NT>>>(fp, embf, Wg, bg);
    k_mv0<<<256, NT, SMEM_BYTES>>>(A);
    k_hs<<<N_ATOMS / NT, NT>>>(Wg + DD * DD, bg + DD);
    k_mv<<<128, NT, SMEM_BYTES>>>();
    k_hs<<<N_ATOMS / NT, NT>>>(Wg + 2 * DD * DD, bg + 2 * DD);
    k_mv<<<128, NT, SMEM_BYTES>>>();
    k_comp<<<1, 512>>>(Wat, bat);

    // ----- join + tail -----
    cudaStreamWaitEvent(0, eJoin, 0);
    k_att<<<L_WORDS / NT, NT>>>(Wat, bat);
    k_final<<<1, NT>>>(Wout, bout, Wint, bint, out);
}

// round 15
// speedup vs baseline: 1.1014x; 1.1014x over previous
#include <cuda_runtime.h>
#include <cstdint>

#define N_ATOMS 4096
#define L_WORDS 65536
#define DD 10
#define KS 23
#define NT 256
// k_mv0: split-K 2 (R11-proven)
#define KB0 2048
#define SMEM0 81920                 // 40 * (KB0/8) * 8
#define MV0ROWS 4
#define MV0TILE 32
// k_mv: split-K 4, same rows/warp
#define KBM 1024
#define SMEMM 40960                 // 40 * (KBM/8) * 8
#define MVROWS 4
#define MVTILE 32
#define CROWS 128                   // CNN rows/block (2 threads/row)

typedef unsigned long long ull;

// ---------------- scratch ----------------
__device__ float g_xs[N_ATOMS * DD];
__device__ ull   g_hs[8 * 5 * (N_ATOMS / 8)];        // hs f32x2, [k8][p][m/8]
__device__ uint4 g_Ab[(size_t)N_ATOMS * N_ATOMS / 8];// A bf16
__device__ float g_pp[4][N_ATOMS * DD];              // split-K partials (max 4)
__device__ float g_cnn[2][L_WORDS * DD];
__device__ float g_comp[DD];
__device__ float g_hatt[DD];
__device__ float g_part[256 * DD];

// ---------------- helpers ----------------
__device__ __forceinline__ ull pack2(float x, float y) {
    ull r; asm("mov.b64 %0, {%1, %2};" : "=l"(r) : "f"(x), "f"(y)); return r;
}
__device__ __forceinline__ void unpack2(ull v, float& x, float& y) {
    asm("mov.b64 {%0, %1}, %2;" : "=f"(x), "=f"(y) : "l"(v));
}
__device__ __forceinline__ void fma2(ull& d, ull a, ull b) {
    asm("fma.rn.f32x2 %0, %1, %2, %0;" : "+l"(d) : "l"(a), "l"(b));
}
__device__ __forceinline__ ull add2(ull a, ull b) {
    ull r; asm("add.rn.f32x2 %0, %1, %2;" : "=l"(r) : "l"(a), "l"(b)); return r;
}
__device__ __forceinline__ unsigned bfpack(float lo, float hi) {
    unsigned r;
    asm("cvt.rn.bf16x2.f32 %0, %1, %2;" : "=r"(r) : "f"(hi), "f"(lo));
    return r;
}

__device__ __forceinline__ void hs_store(int m, const float* x,
                                         const float* Wgl, const float* bgl) {
    int k8 = m & 7, base = m >> 3;
#pragma unroll
    for (int p = 0; p < 5; p++) {
        float h0 = bgl[2 * p], h1 = bgl[2 * p + 1];
#pragma unroll
        for (int c = 0; c < DD; c++) {
            h0 = fmaf(x[c], Wgl[(2 * p) * DD + c], h0);
            h1 = fmaf(x[c], Wgl[(2 * p + 1) * DD + c], h1);
        }
        g_hs[(k8 * 5 + p) * (N_ATOMS / 8) + base] =
            pack2(fmaxf(h0, 0.f), fmaxf(h1, 0.f));
    }
}

// ---------------- GNN chain kernels ----------------
// k_pre: 2 threads per atom (even tid: gather+xs low half & hs p=0..2;
// odd: high half & p=3..4). Simpler: thread t handles atom m = t>>1, and
// the two threads split the 5 p-values 3/2; both load full x (10 floats).
__global__ void __launch_bounds__(NT) k_pre(const int* __restrict__ fp,
                                            const float* __restrict__ embf,
                                            const float* __restrict__ Wg,
                                            const float* __restrict__ bg) {
    int t = blockIdx.x * NT + threadIdx.x;
    int m = t >> 1, half = t & 1;
    const float* src = embf + (size_t)fp[m] * DD;
    float x[DD];
#pragma unroll
    for (int c = 0; c < DD; c++) x[c] = src[c];
    if (half == 0) {
#pragma unroll
        for (int c = 0; c < DD; c++) g_xs[m * DD + c] = x[c];
    }
    int k8 = m & 7, base = m >> 3;
    int p0 = half * 3, p1 = half ? 5 : 3;   // 0..2 / 3..4
    for (int p = p0; p < p1; p++) {
        float h0 = bg[2 * p], h1 = bg[2 * p + 1];
#pragma unroll
        for (int c = 0; c < DD; c++) {
            h0 = fmaf(x[c], Wg[(2 * p) * DD + c], h0);
            h1 = fmaf(x[c], Wg[(2 * p + 1) * DD + c], h1);
        }
        g_hs[(k8 * 5 + p) * (N_ATOMS / 8) + base] =
            pack2(fmaxf(h0, 0.f), fmaxf(h1, 0.f));
    }
}

__global__ void __launch_bounds__(NT) k_hs(const float* __restrict__ Wgl,
                                           const float* __restrict__ bgl, int nsplit) {
    int m = blockIdx.x * NT + threadIdx.x;
    float x[DD];
#pragma unroll
    for (int c = 0; c < DD; c++) {
        float v = g_xs[m * DD + c];
        for (int kb = 0; kb < nsplit; kb++) v += g_pp[kb][m * DD + c];
        g_xs[m * DD + c] = v;
        x[c] = v;
    }
    hs_store(m, x, Wgl, bgl);
}

// layer0 mv: fp32 A read, bf16 write, 32-row tiles, grid 256 (R11 config)
__global__ void __launch_bounds__(NT, 2) k_mv0(const float* __restrict__ A) {
    extern __shared__ char smem_raw[];
    ull* sh = (ull*)smem_raw;
    const int tid = threadIdx.x;
    const int rowblk = blockIdx.x & 127, kb = blockIdx.x >> 7;
    for (int i = tid; i < 40 * (KB0 / 8); i += NT) {
        int kp = i / (KB0 / 8), j = i % (KB0 / 8);
        sh[i] = g_hs[kp * (N_ATOMS / 8) + kb * (KB0 / 8) + j];
    }
    __syncthreads();

    const int warp = tid >> 5, lane = tid & 31;
    const int row0 = rowblk * MV0TILE + warp * MV0ROWS;
    float* pout = g_pp[kb];

    const float4* Af[MV0ROWS];
    uint4* Ao[MV0ROWS];
#pragma unroll
    for (int r = 0; r < MV0ROWS; r++) {
        Af[r] = (const float4*)A + (size_t)(row0 + r) * (N_ATOMS / 4) + kb * (KB0 / 4);
        Ao[r] = g_Ab + (size_t)(row0 + r) * (N_ATOMS / 8) + kb * (KB0 / 8);
    }

    ull acc[MV0ROWS][5];
#pragma unroll
    for (int r = 0; r < MV0ROWS; r++)
#pragma unroll
        for (int p = 0; p < 5; p++) acc[r][p] = 0ull;

    for (int it = 0; it < KB0 / 256; it++) {
        int q = it * 32 + lane;
        float4 lo[MV0ROWS], hi[MV0ROWS];
#pragma unroll
        for (int r = 0; r < MV0ROWS; r++) {
            lo[r] = Af[r][2 * q];
            hi[r] = Af[r][2 * q + 1];
            uint4 o;
            o.x = bfpack(lo[r].x, lo[r].y);
            o.y = bfpack(lo[r].z, lo[r].w);
            o.z = bfpack(hi[r].x, hi[r].y);
            o.w = bfpack(hi[r].z, hi[r].w);
            Ao[r][q] = o;
        }
#pragma unroll
        for (int k8 = 0; k8 < 8; k8++) {
            ull h[5];
#pragma unroll
            for (int p = 0; p < 5; p++)
                h[p] = sh[(k8 * 5 + p) * (KB0 / 8) + q];
#pragma unroll
            for (int r = 0; r < MV0ROWS; r++) {
                float av = (k8 == 0) ? lo[r].x : (k8 == 1) ? lo[r].y
                         : (k8 == 2) ? lo[r].z : (k8 == 3) ? lo[r].w
                         : (k8 == 4) ? hi[r].x : (k8 == 5) ? hi[r].y
                         : (k8 == 6) ? hi[r].z : hi[r].w;
                ull v = pack2(av, av);
#pragma unroll
                for (int p = 0; p < 5; p++) fma2(acc[r][p], v, h[p]);
            }
        }
    }

#pragma unroll
    for (int r = 0; r < MV0ROWS; r++) {
        float f[DD];
#pragma unroll
        for (int p = 0; p < 5; p++) unpack2(acc[r][p], f[2 * p], f[2 * p + 1]);
#pragma unroll
        for (int d = 0; d < DD; d++)
#pragma unroll
            for (int o = 16; o > 0; o >>= 1)
                f[d] += __shfl_down_sync(0xffffffffu, f[d], o);
        if (lane == 0)
#pragma unroll
            for (int d = 0; d < DD; d++) pout[(row0 + r) * DD + d] = f[d];
    }
}

// layers 1,2 mv: bf16 A uint4 loads (R11 inner loop), split-K 4, grid 512
__global__ void __launch_bounds__(NT, 3) k_mv() {
    extern __shared__ char smem_raw[];
    ull* sh = (ull*)smem_raw;
    const int tid = threadIdx.x;
    const int rowblk = blockIdx.x & 127, kb = blockIdx.x >> 7;
    for (int i = tid; i < 40 * (KBM / 8); i += NT) {
        int kp = i / (KBM / 8), j = i % (KBM / 8);
        sh[i] = g_hs[kp * (N_ATOMS / 8) + kb * (KBM / 8) + j];
    }
    __syncthreads();

    const int warp = tid >> 5, lane = tid & 31;
    const int row0 = rowblk * MVTILE + warp * MVROWS;
    float* pout = g_pp[kb];
    const int rstride = N_ATOMS / 8;
    const uint4* Abase = g_Ab + (size_t)row0 * rstride + kb * (KBM / 8);

    ull acc[MVROWS][5];
#pragma unroll
    for (int r = 0; r < MVROWS; r++)
#pragma unroll
        for (int p = 0; p < 5; p++) acc[r][p] = 0ull;

    for (int it = 0; it < KBM / 256; it++) {
        int q = it * 32 + lane;
        uint4 a[MVROWS];
#pragma unroll
        for (int r = 0; r < MVROWS; r++) a[r] = Abase[r * rstride + q];
#pragma unroll
        for (int k8 = 0; k8 < 8; k8++) {
            ull h[5];
#pragma unroll
            for (int p = 0; p < 5; p++)
                h[p] = sh[(k8 * 5 + p) * (KBM / 8) + q];
#pragma unroll
            for (int r = 0; r < MVROWS; r++) {
                unsigned w = (k8 < 2) ? a[r].x : (k8 < 4) ? a[r].y
                           : (k8 < 6) ? a[r].z : a[r].w;
                float av = (k8 & 1) ? __uint_as_float(w & 0xffff0000u)
                                    : __uint_as_float(w << 16);
                ull v = pack2(av, av);
#pragma unroll
                for (int p = 0; p < 5; p++) fma2(acc[r][p], v, h[p]);
            }
        }
    }

#pragma unroll
    for (int r = 0; r < MVROWS; r++) {
        float f[DD];
#pragma unroll
        for (int p = 0; p < 5; p++) unpack2(acc[r][p], f[2 * p], f[2 * p + 1]);
#pragma unroll
        for (int d = 0; d < DD; d++)
#pragma unroll
            for (int o = 16; o > 0; o >>= 1)
                f[d] += __shfl_down_sync(0xffffffffu, f[d], o);
        if (lane == 0)
#pragma unroll
            for (int d = 0; d < DD; d++) pout[(row0 + r) * DD + d] = f[d];
    }
}

__global__ void __launch_bounds__(512) k_comp(const float* __restrict__ Wat,
                                              const float* __restrict__ bat) {
    __shared__ float red[512 * DD];
    int tid = threadIdx.x;
    float acc[DD];
#pragma unroll
    for (int d = 0; d < DD; d++) acc[d] = 0.f;
    for (int n = tid; n < N_ATOMS; n += 512) {
#pragma unroll
        for (int d = 0; d < DD; d++) {
            float v = g_xs[n * DD + d];
#pragma unroll
            for (int kb = 0; kb < 4; kb++) v += g_pp[kb][n * DD + d];
            acc[d] += v;
        }
    }
#pragma unroll
    for (int d = 0; d < DD; d++) red[tid * DD + d] = acc[d];
    __syncthreads();
    for (int s = 256; s > 0; s >>= 1) {
        if (tid < s) {
#pragma unroll
            for (int d = 0; d < DD; d++) red[tid * DD + d] += red[(tid + s) * DD + d];
        }
        __syncthreads();
    }
    if (tid < DD) {
        float comp = red[tid] * (1.f / N_ATOMS);
        g_comp[tid] = comp;
        float hv = bat[tid];
#pragma unroll
        for (int c = 0; c < DD; c++)
            hv = fmaf(red[c] * (1.f / N_ATOMS), Wat[tid * DD + c], hv);
        g_hatt[tid] = fmaxf(hv, 0.f);
    }
}

// ---------------- CNN chain (exact R11) ----------------
__global__ void __launch_bounds__(NT) k_gather_w(const int* __restrict__ wd,
                                                 const float* __restrict__ emb) {
    int i = blockIdx.x * NT + threadIdx.x;
    int n = i / DD, d = i - n * DD;
    g_cnn[0][i] = emb[(size_t)wd[n] * DD + d];
}

__global__ void __launch_bounds__(NT) k_cnn(int layer, const float* __restrict__ Wc,
                                            const float* __restrict__ bc) {
    __shared__ float sIn[(CROWS + 22) * 11];
    __shared__ ull sW[KS * 50];
    __shared__ ull red[CROWS * 5];
    const int tid = threadIdx.x;
    const int row = tid & (CROWS - 1);
    const int half = tid >> 7;
    const float* in = g_cnn[layer & 1];
    float*       o  = g_cnn[(layer & 1) ^ 1];
    const float* W  = Wc + layer * KS * KS;
    const float bias = bc[layer];

    for (int i = tid; i < KS * 50; i += NT) {
        int dl = i / 50, rem = i % 50, c = rem / 5, p = rem % 5;
        sW[i] = pack2(W[dl * KS + 11 + c - 2 * p], W[dl * KS + 11 + c - 2 * p - 1]);
    }
    int base = blockIdx.x * CROWS - 11;
    for (int i = tid; i < (CROWS + 22) * DD; i += NT) {
        int rr = i / DD, c = i - rr * DD;
        int g = base + rr;
        sIn[rr * 11 + c] = (g >= 0 && g < L_WORDS) ? in[g * DD + c] : 0.f;
    }
    __syncthreads();

    ull acc[5];
    ull b2 = pack2(bias, bias);
#pragma unroll
    for (int p = 0; p < 5; p++) acc[p] = (half == 0) ? b2 : 0ull;
    const int c0 = half * 5;
#pragma unroll 1
    for (int dl = 0; dl < KS; dl++) {
#pragma unroll
        for (int cc = 0; cc < 5; cc++) {
            int c = c0 + cc;
            float xv = sIn[(row + dl) * 11 + c];
            ull x2 = pack2(xv, xv);
#pragma unroll
            for (int p = 0; p < 5; p++) fma2(acc[p], x2, sW[dl * 50 + c * 5 + p]);
        }
    }

    if (half == 1) {
#pragma unroll
        for (int p = 0; p < 5; p++) red[row * 5 + p] = acc[p];
    }
    __syncthreads();
    if (half == 0) {
        int grow = blockIdx.x * CROWS + row;
#pragma unroll
        for (int p = 0; p < 5; p++) {
            ull s = add2(acc[p], red[row * 5 + p]);
            float v0, v1;
            unpack2(s, v0, v1);
            o[grow * DD + 2 * p]     = fmaxf(v0, 0.f);
            o[grow * DD + 2 * p + 1] = fmaxf(v1, 0.f);
        }
    }
}

// ---------------- join kernels ----------------
__global__ void __launch_bounds__(NT) k_att(const float* __restrict__ Wat,
                                            const float* __restrict__ bat) {
    __shared__ float sWat[DD * DD], sbv[DD], shv[DD];
    __shared__ float red[NT * DD];
    const int tid = threadIdx.x;
    if (tid < DD * DD) sWat[tid] = Wat[tid];
    if (tid < DD) { sbv[tid] = bat[tid]; shv[tid] = g_hatt[tid]; }
    __syncthreads();

    int l = blockIdx.x * NT + tid;
    const float* in = g_cnn[1];
    float x[DD];
#pragma unroll
    for (int c = 0; c < DD; c++) x[c] = in[l * DD + c];
    float hp[DD], wl = 0.f;
#pragma unroll
    for (int u = 0; u < DD; u++) {
        float v = sbv[u];
#pragma unroll
        for (int c = 0; c < DD; c++) v = fmaf(x[c], sWat[u * DD + c], v);
        v = fmaxf(v, 0.f);
        hp[u] = v;
        wl = fmaf(shv[u], v, wl);
    }
    wl = tanhf(wl);
#pragma unroll
    for (int d = 0; d < DD; d++) red[tid * DD + d] = wl * hp[d];
    __syncthreads();
    for (int s = 128; s > 0; s >>= 1) {
        if (tid < s) {
#pragma unroll
            for (int d = 0; d < DD; d++) red[tid * DD + d] += red[(tid + s) * DD + d];
        }
        __syncthreads();
    }
    if (tid < DD) g_part[blockIdx.x * DD + tid] = red[tid];
}

__global__ void __launch_bounds__(NT) k_final(const float* __restrict__ Wout,
                                              const float* __restrict__ bout,
                                              const float* __restrict__ Wint,
                                              const float* __restrict__ bint,
                                              float* __restrict__ out) {
    __shared__ float red[NT * DD];
    __shared__ float cat[20];
    const int tid = threadIdx.x;
#pragma unroll
    for (int d = 0; d < DD; d++) red[tid * DD + d] = g_part[tid * DD + d];
    __syncthreads();
    for (int s = 128; s > 0; s >>= 1) {
        if (tid < s) {
#pragma unroll
            for (int d = 0; d < DD; d++) red[tid * DD + d] += red[(tid + s) * DD + d];
        }
        __syncthreads();
    }
    if (tid < DD) cat[tid] = g_comp[tid];
    if (tid >= DD && tid < 20) cat[tid] = red[tid - DD] * (1.f / L_WORDS);
    __syncthreads();
    if (tid < 32) {
        for (int j = 0; j < 3; j++) {
            float v = 0.f;
            if (tid < 20) {
                v = bout[j * 20 + tid];
                for (int c = 0; c < 20; c++)
                    v = fmaf(cat[c], Wout[j * 400 + tid * 20 + c], v);
                v = fmaxf(v, 0.f);
            }
            __syncwarp();
            if (tid < 20) cat[tid] = v;
            __syncwarp();
        }
        if (tid < 2) {
            float v = bint[tid];
            for (int c = 0; c < 20; c++) v = fmaf(cat[c], Wint[tid * 20 + c], v);
            out[tid] = v;
        }
    }
}

// ---------------- launch: two-branch graph ----------------
extern "C" void kernel_launch(void* const* d_in, const int* in_sizes, int n_in,
                              void* d_out, int out_size) {
    const int*   fp    = (const int*)d_in[0];
    const float* A     = (const float*)d_in[1];
    const int*   words = (const int*)d_in[2];
    const float* embf  = (const float*)d_in[3];
    const float* embw  = (const float*)d_in[4];
    const float* Wg    = (const float*)d_in[5];
    const float* bg    = (const float*)d_in[6];
    const float* Wc    = (const float*)d_in[7];
    const float* bc    = (const float*)d_in[8];
    const float* Wat   = (const float*)d_in[9];
    const float* bat   = (const float*)d_in[10];
    const float* Wout  = (const float*)d_in[11];
    const float* bout  = (const float*)d_in[12];
    const float* Wint  = (const float*)d_in[13];
    const float* bint  = (const float*)d_in[14];
    float* out = (float*)d_out;

    cudaFuncSetAttribute(k_mv0, cudaFuncAttributeMaxDynamicSharedMemorySize, SMEM0);
    cudaFuncSetAttribute(k_mv,  cudaFuncAttributeMaxDynamicSharedMemorySize, SMEMM);

    cudaStream_t sC;
    cudaStreamCreateWithFlags(&sC, cudaStreamNonBlocking);
    cudaEvent_t eFork, eJoin;
    cudaEventCreateWithFlags(&eFork, cudaEventDisableTiming);
    cudaEventCreateWithFlags(&eJoin, cudaEventDisableTiming);

    cudaEventRecord(eFork, 0);
    cudaStreamWaitEvent(sC, eFork, 0);

    // ----- CNN branch (exact R11) -----
    k_gather_w<<<L_WORDS * DD / NT, NT, 0, sC>>>(words, embw);
    k_cnn<<<L_WORDS / CROWS, NT, 0, sC>>>(0, Wc, bc);
    k_cnn<<<L_WORDS / CROWS, NT, 0, sC>>>(1, Wc, bc);
    k_cnn<<<L_WORDS / CROWS, NT, 0, sC>>>(2, Wc, bc);
    cudaEventRecord(eJoin, sC);

    // ----- GNN branch -----
    k_pre<<<2 * N_ATOMS / NT, NT>>>(fp, embf, Wg, bg);
    k_mv0<<<256, NT, SMEM0>>>(A);                       // writes g_pp[0..1], g_Ab
    k_hs<<<N_ATOMS / NT, NT>>>(Wg + DD * DD, bg + DD, 2);
    k_mv<<<512, NT, SMEMM>>>();                         // writes g_pp[0..3]
    k_hs<<<N_ATOMS / NT, NT>>>(Wg + 2 * DD * DD, bg + 2 * DD, 4);
    k_mv<<<512, NT, SMEMM>>>();
    k_comp<<<1, 512>>>(Wat, bat);

    // ----- join + tail -----
    cudaStreamWaitEvent(0, eJoin, 0);
    k_att<<<L_WORDS / NT, NT>>>(Wat, bat);
    k_final<<<1, NT>>>(Wout, bout, Wint, bint, out);
}

// round 16
// speedup vs baseline: 1.2240x; 1.1113x over previous
#include <cuda_runtime.h>
#include <cstdint>

#define N_ATOMS 4096
#define L_WORDS 65536
#define DD 10
#define KS 23
#define KSPLIT 2
#define KCHUNK (N_ATOMS / KSPLIT)   // 2048
#define NT 256
#define SMEM_BYTES 81920            // 40 * (KCHUNK/8) * 8
#define MVROWS 4
#define MVTILE 32
#define CROWS 128                   // CNN rows/block (2 threads/row)

typedef unsigned long long ull;

// ---------------- scratch ----------------
__device__ float g_xs[N_ATOMS * DD];
__device__ ull   g_hs[8 * 5 * (N_ATOMS / 8)];        // hs f32x2, [k8][p][m/8]
__device__ uint4 g_Ab[(size_t)N_ATOMS * N_ATOMS / 8];// A bf16
__device__ float g_pp[KSPLIT][N_ATOMS * DD];
__device__ float g_cnn[2][L_WORDS * DD];
__device__ float g_comp[DD];
__device__ float g_hatt[DD];
__device__ float g_part[256 * DD];

// ---------------- helpers ----------------
__device__ __forceinline__ ull pack2(float x, float y) {
    ull r; asm("mov.b64 %0, {%1, %2};" : "=l"(r) : "f"(x), "f"(y)); return r;
}
__device__ __forceinline__ void unpack2(ull v, float& x, float& y) {
    asm("mov.b64 {%0, %1}, %2;" : "=f"(x), "=f"(y) : "l"(v));
}
__device__ __forceinline__ void fma2(ull& d, ull a, ull b) {
    asm("fma.rn.f32x2 %0, %1, %2, %0;" : "+l"(d) : "l"(a), "l"(b));
}
__device__ __forceinline__ ull add2(ull a, ull b) {
    ull r; asm("add.rn.f32x2 %0, %1, %2;" : "=l"(r) : "l"(a), "l"(b)); return r;
}
__device__ __forceinline__ unsigned bfpack(float lo, float hi) {
    unsigned r;
    asm("cvt.rn.bf16x2.f32 %0, %1, %2;" : "=r"(r) : "f"(hi), "f"(lo));
    return r;
}

__device__ __forceinline__ void hs_store(int m, const float* x,
                                         const float* Wgl, const float* bgl) {
    int k8 = m & 7, base = m >> 3;
#pragma unroll
    for (int p = 0; p < 5; p++) {
        float h0 = bgl[2 * p], h1 = bgl[2 * p + 1];
#pragma unroll
        for (int c = 0; c < DD; c++) {
            h0 = fmaf(x[c], Wgl[(2 * p) * DD + c], h0);
            h1 = fmaf(x[c], Wgl[(2 * p + 1) * DD + c], h1);
        }
        g_hs[(k8 * 5 + p) * (N_ATOMS / 8) + base] =
            pack2(fmaxf(h0, 0.f), fmaxf(h1, 0.f));
    }
}

__device__ __forceinline__ void fill_hs(ull* sh, int kb) {
    for (int i = threadIdx.x; i < 40 * (KCHUNK / 8); i += NT) {
        int kp = i / (KCHUNK / 8), j = i % (KCHUNK / 8);
        sh[i] = g_hs[kp * (N_ATOMS / 8) + kb * (KCHUNK / 8) + j];
    }
    __syncthreads();
}

// ---------------- GNN chain kernels ----------------
// 2 threads/atom: both load x; half 0 writes xs and p=0..2, half 1 p=3..4
__global__ void __launch_bounds__(NT) k_pre(const int* __restrict__ fp,
                                            const float* __restrict__ embf,
                                            const float* __restrict__ Wg,
                                            const float* __restrict__ bg) {
    int t = blockIdx.x * NT + threadIdx.x;
    int m = t >> 1, half = t & 1;
    const float* src = embf + (size_t)fp[m] * DD;
    float x[DD];
#pragma unroll
    for (int c = 0; c < DD; c++) x[c] = src[c];
    if (half == 0) {
#pragma unroll
        for (int c = 0; c < DD; c++) g_xs[m * DD + c] = x[c];
    }
    int k8 = m & 7, base = m >> 3;
    int p0 = half * 3, p1 = half ? 5 : 3;
    for (int p = p0; p < p1; p++) {
        float h0 = bg[2 * p], h1 = bg[2 * p + 1];
#pragma unroll
        for (int c = 0; c < DD; c++) {
            h0 = fmaf(x[c], Wg[(2 * p) * DD + c], h0);
            h1 = fmaf(x[c], Wg[(2 * p + 1) * DD + c], h1);
        }
        g_hs[(k8 * 5 + p) * (N_ATOMS / 8) + base] =
            pack2(fmaxf(h0, 0.f), fmaxf(h1, 0.f));
    }
}

__global__ void __launch_bounds__(NT) k_hs(const float* __restrict__ Wgl,
                                           const float* __restrict__ bgl) {
    int m = blockIdx.x * NT + threadIdx.x;
    float x[DD];
#pragma unroll
    for (int c = 0; c < DD; c++) {
        float v = g_xs[m * DD + c] + g_pp[0][m * DD + c] + g_pp[1][m * DD + c];
        g_xs[m * DD + c] = v;
        x[c] = v;
    }
    hs_store(m, x, Wgl, bgl);
}

// layer0 mv: fp32 A read, bf16 write, 32-row tiles, grid 256 (exact R11)
__global__ void __launch_bounds__(NT, 2) k_mv0(const float* __restrict__ A) {
    extern __shared__ char smem_raw[];
    ull* sh = (ull*)smem_raw;
    const int tid = threadIdx.x;
    const int rowblk = blockIdx.x & 127, kb = blockIdx.x >> 7;
    fill_hs(sh, kb);

    const int warp = tid >> 5, lane = tid & 31;
    const int row0 = rowblk * MVTILE + warp * MVROWS;
    float* pout = g_pp[kb];

    const float4* Af[MVROWS];
    uint4* Ao[MVROWS];
#pragma unroll
    for (int r = 0; r < MVROWS; r++) {
        Af[r] = (const float4*)A + (size_t)(row0 + r) * (N_ATOMS / 4) + kb * (KCHUNK / 4);
        Ao[r] = g_Ab + (size_t)(row0 + r) * (N_ATOMS / 8) + kb * (KCHUNK / 8);
    }

    ull acc[MVROWS][5];
#pragma unroll
    for (int r = 0; r < MVROWS; r++)
#pragma unroll
        for (int p = 0; p < 5; p++) acc[r][p] = 0ull;

    for (int it = 0; it < KCHUNK / 256; it++) {
        int q = it * 32 + lane;
        float4 lo[MVROWS], hi[MVROWS];
#pragma unroll
        for (int r = 0; r < MVROWS; r++) {
            lo[r] = Af[r][2 * q];
            hi[r] = Af[r][2 * q + 1];
            uint4 o;
            o.x = bfpack(lo[r].x, lo[r].y);
            o.y = bfpack(lo[r].z, lo[r].w);
            o.z = bfpack(hi[r].x, hi[r].y);
            o.w = bfpack(hi[r].z, hi[r].w);
            Ao[r][q] = o;
        }
#pragma unroll
        for (int k8 = 0; k8 < 8; k8++) {
            ull h[5];
#pragma unroll
            for (int p = 0; p < 5; p++)
                h[p] = sh[(k8 * 5 + p) * (KCHUNK / 8) + q];
#pragma unroll
            for (int r = 0; r < MVROWS; r++) {
                float av = (k8 == 0) ? lo[r].x : (k8 == 1) ? lo[r].y
                         : (k8 == 2) ? lo[r].z : (k8 == 3) ? lo[r].w
                         : (k8 == 4) ? hi[r].x : (k8 == 5) ? hi[r].y
                         : (k8 == 6) ? hi[r].z : hi[r].w;
                ull v = pack2(av, av);
#pragma unroll
                for (int p = 0; p < 5; p++) fma2(acc[r][p], v, h[p]);
            }
        }
    }

#pragma unroll
    for (int r = 0; r < MVROWS; r++) {
        float f[DD];
#pragma unroll
        for (int p = 0; p < 5; p++) unpack2(acc[r][p], f[2 * p], f[2 * p + 1]);
#pragma unroll
        for (int d = 0; d < DD; d++)
#pragma unroll
            for (int o = 16; o > 0; o >>= 1)
                f[d] += __shfl_down_sync(0xffffffffu, f[d], o);
        if (lane == 0)
#pragma unroll
            for (int d = 0; d < DD; d++) pout[(row0 + r) * DD + d] = f[d];
    }
}

// layers 1,2 mv: bf16 A with prefetch, 32-row tiles, grid 256 (exact R11)
__global__ void __launch_bounds__(NT, 2) k_mv() {
    extern __shared__ char smem_raw[];
    ull* sh = (ull*)smem_raw;
    const int tid = threadIdx.x;
    const int rowblk = blockIdx.x & 127, kb = blockIdx.x >> 7;
    fill_hs(sh, kb);

    const int warp = tid >> 5, lane = tid & 31;
    const int row0 = rowblk * MVTILE + warp * MVROWS;
    float* pout = g_pp[kb];
    const int rstride = N_ATOMS / 8;
    const uint4* Abase = g_Ab + (size_t)row0 * rstride + kb * (KCHUNK / 8);

    ull acc[MVROWS][5];
#pragma unroll
    for (int r = 0; r < MVROWS; r++)
#pragma unroll
        for (int p = 0; p < 5; p++) acc[r][p] = 0ull;

    uint4 a[MVROWS];
#pragma unroll
    for (int r = 0; r < MVROWS; r++) a[r] = Abase[r * rstride + lane];

    for (int it = 0; it < KCHUNK / 256; it++) {
        int q = it * 32 + lane;
        uint4 nxt[MVROWS];
        if (it + 1 < KCHUNK / 256) {
#pragma unroll
            for (int r = 0; r < MVROWS; r++) nxt[r] = Abase[r * rstride + q + 32];
        }
#pragma unroll
        for (int k8 = 0; k8 < 8; k8++) {
            ull h[5];
#pragma unroll
            for (int p = 0; p < 5; p++)
                h[p] = sh[(k8 * 5 + p) * (KCHUNK / 8) + q];
#pragma unroll
            for (int r = 0; r < MVROWS; r++) {
                unsigned w = (k8 < 2) ? a[r].x : (k8 < 4) ? a[r].y
                           : (k8 < 6) ? a[r].z : a[r].w;
                float av = (k8 & 1) ? __uint_as_float(w & 0xffff0000u)
                                    : __uint_as_float(w << 16);
                ull v = pack2(av, av);
#pragma unroll
                for (int p = 0; p < 5; p++) fma2(acc[r][p], v, h[p]);
            }
        }
#pragma unroll
        for (int r = 0; r < MVROWS; r++) a[r] = nxt[r];
    }

#pragma unroll
    for (int r = 0; r < MVROWS; r++) {
        float f[DD];
#pragma unroll
        for (int p = 0; p < 5; p++) unpack2(acc[r][p], f[2 * p], f[2 * p + 1]);
#pragma unroll
        for (int d = 0; d < DD; d++)
#pragma unroll
            for (int o = 16; o > 0; o >>= 1)
                f[d] += __shfl_down_sync(0xffffffffu, f[d], o);
        if (lane == 0)
#pragma unroll
            for (int d = 0; d < DD; d++) pout[(row0 + r) * DD + d] = f[d];
    }
}

__global__ void __launch_bounds__(512) k_comp(const float* __restrict__ Wat,
                                              const float* __restrict__ bat) {
    __shared__ float red[512 * DD];
    int tid = threadIdx.x;
    float acc[DD];
#pragma unroll
    for (int d = 0; d < DD; d++) acc[d] = 0.f;
    for (int n = tid; n < N_ATOMS; n += 512)
#pragma unroll
        for (int d = 0; d < DD; d++)
            acc[d] += g_xs[n * DD + d] + g_pp[0][n * DD + d] + g_pp[1][n * DD + d];
#pragma unroll
    for (int d = 0; d < DD; d++) red[tid * DD + d] = acc[d];
    __syncthreads();
    for (int s = 256; s > 0; s >>= 1) {
        if (tid < s) {
#pragma unroll
            for (int d = 0; d < DD; d++) red[tid * DD + d] += red[(tid + s) * DD + d];
        }
        __syncthreads();
    }
    if (tid < DD) {
        float comp = red[tid] * (1.f / N_ATOMS);
        g_comp[tid] = comp;
        float hv = bat[tid];
#pragma unroll
        for (int c = 0; c < DD; c++)
            hv = fmaf(red[c] * (1.f / N_ATOMS), Wat[tid * DD + c], hv);
        g_hatt[tid] = fmaxf(hv, 0.f);
    }
}

// ---------------- CNN chain ----------------
// layer 0: gather fused (reads embw[words[.]]); layer 2: emits hp = relu(x@Wat^T+bat)
__global__ void __launch_bounds__(NT) k_cnn(int layer, const float* __restrict__ Wc,
                                            const float* __restrict__ bc,
                                            const int* __restrict__ words,
                                            const float* __restrict__ embw,
                                            const float* __restrict__ Wat,
                                            const float* __restrict__ bat) {
    __shared__ float sIn[(CROWS + 22) * 11];
    __shared__ ull sW[KS * 50];
    __shared__ ull red[CROWS * 5];
    __shared__ float sWat[DD * DD], sbv[DD];
    const int tid = threadIdx.x;
    const int row = tid & (CROWS - 1);
    const int half = tid >> 7;
    const float* in = g_cnn[layer & 1];
    float*       o  = g_cnn[(layer & 1) ^ 1];
    const float* W  = Wc + layer * KS * KS;
    const float bias = bc[layer];
    const bool fuse_att = (layer == 2);

    for (int i = tid; i < KS * 50; i += NT) {
        int dl = i / 50, rem = i % 50, c = rem / 5, p = rem % 5;
        sW[i] = pack2(W[dl * KS + 11 + c - 2 * p], W[dl * KS + 11 + c - 2 * p - 1]);
    }
    if (fuse_att) {
        if (tid < DD * DD) sWat[tid] = Wat[tid];
        if (tid < DD) sbv[tid] = bat[tid];
    }
    int base = blockIdx.x * CROWS - 11;
    if (layer == 0) {
        for (int i = tid; i < (CROWS + 22) * DD; i += NT) {
            int rr = i / DD, c = i - rr * DD;
            int g = base + rr;
            sIn[rr * 11 + c] =
                (g >= 0 && g < L_WORDS) ? embw[(size_t)words[g] * DD + c] : 0.f;
        }
    } else {
        for (int i = tid; i < (CROWS + 22) * DD; i += NT) {
            int rr = i / DD, c = i - rr * DD;
            int g = base + rr;
            sIn[rr * 11 + c] = (g >= 0 && g < L_WORDS) ? in[g * DD + c] : 0.f;
        }
    }
    __syncthreads();

    ull acc[5];
    ull b2 = pack2(bias, bias);
#pragma unroll
    for (int p = 0; p < 5; p++) acc[p] = (half == 0) ? b2 : 0ull;
    const int c0 = half * 5;
#pragma unroll 1
    for (int dl = 0; dl < KS; dl++) {
#pragma unroll
        for (int cc = 0; cc < 5; cc++) {
            int c = c0 + cc;
            float xv = sIn[(row + dl) * 11 + c];
            ull x2 = pack2(xv, xv);
#pragma unroll
            for (int p = 0; p < 5; p++) fma2(acc[p], x2, sW[dl * 50 + c * 5 + p]);
        }
    }

    if (half == 1) {
#pragma unroll
        for (int p = 0; p < 5; p++) red[row * 5 + p] = acc[p];
    }
    __syncthreads();
    if (half == 0) {
        int grow = blockIdx.x * CROWS + row;
        float x[DD];
#pragma unroll
        for (int p = 0; p < 5; p++) {
            ull s = add2(acc[p], red[row * 5 + p]);
            float v0, v1;
            unpack2(s, v0, v1);
            x[2 * p]     = fmaxf(v0, 0.f);
            x[2 * p + 1] = fmaxf(v1, 0.f);
        }
        if (!fuse_att) {
#pragma unroll
            for (int d = 0; d < DD; d++) o[grow * DD + d] = x[d];
        } else {
            // hp = relu(x @ Wat^T + bat); store hp in place of conv output
#pragma unroll
            for (int u = 0; u < DD; u++) {
                float v = sbv[u];
#pragma unroll
                for (int c = 0; c < DD; c++) v = fmaf(x[c], sWat[u * DD + c], v);
                o[grow * DD + u] = fmaxf(v, 0.f);
            }
        }
    }
}

// ---------------- join kernels ----------------
// post-join attention: hp already computed; only tanh(h.hp) and accumulate
__global__ void __launch_bounds__(NT) k_att() {
    __shared__ float shv[DD];
    __shared__ float red[NT * DD];
    const int tid = threadIdx.x;
    if (tid < DD) shv[tid] = g_hatt[tid];
    __syncthreads();

    int l = blockIdx.x * NT + tid;
    const float* hp_in = g_cnn[1];
    float hp[DD], wl = 0.f;
#pragma unroll
    for (int u = 0; u < DD; u++) {
        hp[u] = hp_in[l * DD + u];
        wl = fmaf(shv[u], hp[u], wl);
    }
    wl = tanhf(wl);
#pragma unroll
    for (int d = 0; d < DD; d++) red[tid * DD + d] = wl * hp[d];
    __syncthreads();
    for (int s = 128; s > 0; s >>= 1) {
        if (tid < s) {
#pragma unroll
            for (int d = 0; d < DD; d++) red[tid * DD + d] += red[(tid + s) * DD + d];
        }
        __syncthreads();
    }
    if (tid < DD) g_part[blockIdx.x * DD + tid] = red[tid];
}

__global__ void __launch_bounds__(NT) k_final(const float* __restrict__ Wout,
                                              const float* __restrict__ bout,
                                              const float* __restrict__ Wint,
                                              const float* __restrict__ bint,
                                              float* __restrict__ out) {
    __shared__ float red[NT * DD];
    __shared__ float cat[20];
    const int tid = threadIdx.x;
#pragma unroll
    for (int d = 0; d < DD; d++) red[tid * DD + d] = g_part[tid * DD + d];
    __syncthreads();
    for (int s = 128; s > 0; s >>= 1) {
        if (tid < s) {
#pragma unroll
            for (int d = 0; d < DD; d++) red[tid * DD + d] += red[(tid + s) * DD + d];
        }
        __syncthreads();
    }
    if (tid < DD) cat[tid] = g_comp[tid];
    if (tid >= DD && tid < 20) cat[tid] = red[tid - DD] * (1.f / L_WORDS);
    __syncthreads();
    if (tid < 32) {
        for (int j = 0; j < 3; j++) {
            float v = 0.f;
            if (tid < 20) {
                v = bout[j * 20 + tid];
                for (int c = 0; c < 20; c++)
                    v = fmaf(cat[c], Wout[j * 400 + tid * 20 + c], v);
                v = fmaxf(v, 0.f);
            }
            __syncwarp();
            if (tid < 20) cat[tid] = v;
            __syncwarp();
        }
        if (tid < 2) {
            float v = bint[tid];
            for (int c = 0; c < 20; c++) v = fmaf(cat[c], Wint[tid * 20 + c], v);
            out[tid] = v;
        }
    }
}

// ---------------- launch: two-branch graph ----------------
extern "C" void kernel_launch(void* const* d_in, const int* in_sizes, int n_in,
                              void* d_out, int out_size) {
    const int*   fp    = (const int*)d_in[0];
    const float* A     = (const float*)d_in[1];
    const int*   words = (const int*)d_in[2];
    const float* embf  = (const float*)d_in[3];
    const float* embw  = (const float*)d_in[4];
    const float* Wg    = (const float*)d_in[5];
    const float* bg    = (const float*)d_in[6];
    const float* Wc    = (const float*)d_in[7];
    const float* bc    = (const float*)d_in[8];
    const float* Wat   = (const float*)d_in[9];
    const float* bat   = (const float*)d_in[10];
    const float* Wout  = (const float*)d_in[11];
    const float* bout  = (const float*)d_in[12];
    const float* Wint  = (const float*)d_in[13];
    const float* bint  = (const float*)d_in[14];
    float* out = (float*)d_out;

    cudaFuncSetAttribute(k_mv0, cudaFuncAttributeMaxDynamicSharedMemorySize, SMEM_BYTES);
    cudaFuncSetAttribute(k_mv,  cudaFuncAttributeMaxDynamicSharedMemorySize, SMEM_BYTES);

    cudaStream_t sC;
    cudaStreamCreateWithFlags(&sC, cudaStreamNonBlocking);
    cudaEvent_t eFork, eJoin;
    cudaEventCreateWithFlags(&eFork, cudaEventDisableTiming);
    cudaEventCreateWithFlags(&eJoin, cudaEventDisableTiming);

    cudaEventRecord(eFork, 0);
    cudaStreamWaitEvent(sC, eFork, 0);

    // ----- CNN branch (gather fused into L0; att matmul fused into L2) -----
    k_cnn<<<L_WORDS / CROWS, NT, 0, sC>>>(0, Wc, bc, words, embw, Wat, bat);
    k_cnn<<<L_WORDS / CROWS, NT, 0, sC>>>(1, Wc, bc, words, embw, Wat, bat);
    k_cnn<<<L_WORDS / CROWS, NT, 0, sC>>>(2, Wc, bc, words, embw, Wat, bat);
    cudaEventRecord(eJoin, sC);

    // ----- GNN branch (exact R11 core) -----
    k_pre<<<2 * N_ATOMS / NT, NT>>>(fp, embf, Wg, bg);
    k_mv0<<<256, NT, SMEM_BYTES>>>(A);
    k_hs<<<N_ATOMS / NT, NT>>>(Wg + DD * DD, bg + DD);
    k_mv<<<256, NT, SMEM_BYTES>>>();
    k_hs<<<N_ATOMS / NT, NT>>>(Wg + 2 * DD * DD, bg + 2 * DD);
    k_mv<<<256, NT, SMEM_BYTES>>>();
    k_comp<<<1, 512>>>(Wat, bat);

    // ----- join + tail -----
    cudaStreamWaitEvent(0, eJoin, 0);
    k_att<<<L_WORDS / NT, NT>>>();
    k_final<<<1, NT>>>(Wout, bout, Wint, bint, out);
}